// round 11
// baseline (speedup 1.0000x reference)
#include <cuda_runtime.h>
#include <cstdint>

// CASSI forward: R9 kernel body (TPB=128, simple rotation reduce) +
// R10 halo seeding (single launch, no atomics) + 3-deep TMA ring.
//
// Grid (2, 1024): block (h, m) computes y[m, c], h=0: c in [0,512),
// h=1: c in [512, 1087), seeding its diagonal carry from a 63-row halo
// tile (n in [449,512), 16KB TMA; h=0 reads the same rows -> L2 hit).
// Per tile (TN=128 n-rows, 32KB): thread tid accumulates
//   accL -> output c = n0 + t*128 + tid  (terms l <= tid)
//   accH -> carry for next tile          (terms l >  tid)
// carry rides in a register; all stores direct, full coverage:
//   [0,512) by h0 tiles, [512,1024) by h1 tiles, [1024,1087) by h1 tail.

#define MM    1024
#define NN    1024
#define LL    64
#define OUTC  (NN + LL - 1)            // 1087
#define TN    128
#define TPB   128
#define HALF  512
#define NTIL  (HALF / TN)              // 4
#define NBUF  3                        // TMA ring depth
#define TILE_BYTES (TN * LL * 4)       // 32768
#define HALO_ROWS  (LL - 1)            // 63
#define HALO_BYTES (HALO_ROWS * LL * 4)

__device__ __forceinline__ uint32_t smem_u32(const void* p)
{
    uint32_t a;
    asm("{ .reg .u64 t; cvta.to.shared.u64 t, %1; cvt.u32.u64 %0, t; }"
        : "=r"(a) : "l"(p));
    return a;
}

__device__ __forceinline__ void mbar_init(uint32_t mb, uint32_t count)
{
    asm volatile("mbarrier.init.shared.b64 [%0], %1;" :: "r"(mb), "r"(count) : "memory");
}

__device__ __forceinline__ void tma_bulk(uint32_t dst, const float* src,
                                         uint32_t bytes, uint32_t mb)
{
    asm volatile("mbarrier.arrive.expect_tx.shared.b64 _, [%0], %1;"
                 :: "r"(mb), "r"(bytes) : "memory");
    asm volatile("cp.async.bulk.shared::cta.global.mbarrier::complete_tx::bytes "
                 "[%0], [%1], %2, [%3];"
                 :: "r"(dst), "l"(src), "r"(bytes), "r"(mb) : "memory");
}

__device__ __forceinline__ void mbar_wait(uint32_t mb, uint32_t parity)
{
    uint32_t done;
    asm volatile(
        "{\n\t"
        ".reg .pred p;\n\t"
        "mbarrier.try_wait.parity.acquire.cta.shared::cta.b64 p, [%1], %2;\n\t"
        "selp.b32 %0, 1, 0, p;\n\t"
        "}"
        : "=r"(done) : "r"(mb), "r"(parity) : "memory");
    if (!done) {
        asm volatile(
            "{\n\t"
            ".reg .pred P1;\n\t"
            "W%=:\n\t"
            "mbarrier.try_wait.parity.acquire.cta.shared::cta.b64 P1, [%0], %1;\n\t"
            "@P1 bra D%=;\n\t"
            "bra W%=;\n\t"
            "D%=:\n\t"
            "}"
            :: "r"(mb), "r"(parity) : "memory");
    }
}

__global__ __launch_bounds__(TPB)
void cassi_halo3_kernel(const float* __restrict__ x,
                        const float* __restrict__ ca,
                        float* __restrict__ y)
{
    extern __shared__ float smem[];
    float* bufs = smem;                            // NBUF * 8192 floats
    float* halo = bufs + NBUF * TN * LL;           // 4032 floats
    float* sca  = halo + HALO_ROWS * LL;           // 512 floats
    float* scah = sca + HALF;                      // 64 floats
    __shared__ __align__(8) uint64_t mbar_store[NBUF + 1];

    const int m   = blockIdx.y;
    const int h   = blockIdx.x;                    // 0 or 1
    const int n0  = h * HALF;
    const int tid = threadIdx.x;

    const float* xbase = x + (size_t)m * (NN * LL);
    const float* xrow  = xbase + (size_t)n0 * LL;
    float*       yrow  = y + (size_t)m * OUTC;

    uint32_t mb[NBUF + 1];
    uint32_t bs[NBUF];
    #pragma unroll
    for (int i = 0; i < NBUF + 1; ++i) mb[i] = smem_u32(&mbar_store[i]);
    #pragma unroll
    for (int i = 0; i < NBUF; ++i) bs[i] = smem_u32(bufs + i * TN * LL);

    if (tid == 0) {
        #pragma unroll
        for (int i = 0; i < NBUF + 1; ++i) mbar_init(mb[i], 1);
    }
    __syncthreads();

    if (tid == 0) {
        tma_bulk(bs[0], xrow,               TILE_BYTES, mb[0]);
        tma_bulk(bs[1], xrow + 1 * TN * LL, TILE_BYTES, mb[1]);
        tma_bulk(bs[2], xrow + 2 * TN * LL, TILE_BYTES, mb[2]);
        if (h == 1)
            tma_bulk(smem_u32(halo), xbase + (size_t)(n0 - HALO_ROWS) * LL,
                     HALO_BYTES, mb[NBUF]);
    }

    // Stage ca for this half (+ halo ca for h=1).
    #pragma unroll
    for (int i = tid; i < HALF; i += TPB)
        sca[i] = ca[m * NN + n0 + i];
    if (h == 1 && tid < HALO_ROWS)
        scah[tid] = ca[m * NN + (n0 - HALO_ROWS) + tid];
    __syncthreads();

    // Seed carry for h=1 from the halo tile:
    //   carry[tid] = sum_{k=tid}^{62} halo[k][63+tid-k] * scah[k]
    float carry = 0.0f;
    if (h == 1) {
        mbar_wait(mb[NBUF], 0);
        if (tid < HALO_ROWS) {
            #pragma unroll
            for (int k = 0; k < HALO_ROWS; ++k) {
                if (k >= tid)
                    carry = fmaf(halo[k * LL + (HALO_ROWS + tid - k)], scah[k], carry);
            }
        }
    }

    #pragma unroll 1
    for (int t = 0; t < NTIL; ++t) {
        const int      b      = (t < NBUF) ? t : t - NBUF;   // t % 3 for t<=5
        const uint32_t parity = (t < NBUF) ? 0u : 1u;
        const float*   cur    = bufs + b * TN * LL;

        mbar_wait(mb[b], parity);

        const float* scat = sca + t * TN;
        float accL = carry;                  // carry == 0 for tid >= LL-1
        float accH = 0.0f;
        #pragma unroll
        for (int j = 0; j < LL; ++j) {
            const int  l   = (tid + j) & (LL - 1);
            const bool low = (l <= tid);
            const int  n   = low ? (tid - l) : (tid + TN - l);
            const float v  = cur[n * LL + l];
            if (low) accL = fmaf(v, scat[n], accL);
            else     accH = fmaf(v, scat[n], accH);
        }
        yrow[n0 + t * TN + tid] = accL;
        carry = accH;

        __syncthreads();                     // all threads done reading `cur`

        if (tid == 0 && t + NBUF < NTIL)
            tma_bulk(bs[b], xrow + (size_t)(t + NBUF) * TN * LL,
                     TILE_BYTES, mb[b]);
    }

    // Tail: h=1 writes c in [NN, NN+LL-1); h=0's final carry is discarded
    // (those columns are fully computed by h=1 via the halo seed).
    if (h == 1 && tid < LL - 1)
        yrow[NN + tid] = carry;
}

extern "C" void kernel_launch(void* const* d_in, const int* in_sizes, int n_in,
                              void* d_out, int out_size)
{
    const float* x  = (const float*)d_in[0];
    const float* ca = (const float*)d_in[1];
    float* y        = (float*)d_out;

    const int smem_bytes =
        (NBUF * TN * LL + HALO_ROWS * LL + HALF + 64) * sizeof(float);

    cudaFuncSetAttribute(cassi_halo3_kernel,
                         cudaFuncAttributeMaxDynamicSharedMemorySize,
                         smem_bytes);

    cassi_halo3_kernel<<<dim3(2, MM), TPB, smem_bytes>>>(x, ca, y);
}

// round 12
// speedup vs baseline: 1.4126x; 1.4126x over previous
#include <cuda_runtime.h>
#include <cstdint>

// CASSI forward: R9 kernel body (TPB=128, 2-deep TMA ring, simple rotation
// reduce) + R10 halo seeding (single launch, no atomics, no zero-init).
// smem = 2*32KB ring + 16KB halo + ~2.3KB ca = 84.0KB -> 2 blocks/SM.
//
// Grid (2, 1024): block (h, m) computes y[m, c], h=0: c in [0,512),
// h=1: c in [512,1087), seeding its diagonal carry from a 63-row halo
// tile (n in [449,512); h=0 streams the same rows -> L2 hit).
// Per tile (TN=128 n-rows): thread tid accumulates
//   accL -> output c = n0 + t*128 + tid  (terms l <= tid)
//   accH -> carry for next tile          (terms l >  tid)

#define MM    1024
#define NN    1024
#define LL    64
#define OUTC  (NN + LL - 1)            // 1087
#define TN    128
#define TPB   128
#define HALF  512
#define NTIL  (HALF / TN)              // 4
#define TILE_BYTES (TN * LL * 4)       // 32768
#define HALO_ROWS  (LL - 1)            // 63
#define HALO_BYTES (HALO_ROWS * LL * 4)  // 16128

__device__ __forceinline__ uint32_t smem_u32(const void* p)
{
    uint32_t a;
    asm("{ .reg .u64 t; cvta.to.shared.u64 t, %1; cvt.u32.u64 %0, t; }"
        : "=r"(a) : "l"(p));
    return a;
}

__device__ __forceinline__ void mbar_init(uint32_t mb, uint32_t count)
{
    asm volatile("mbarrier.init.shared.b64 [%0], %1;" :: "r"(mb), "r"(count) : "memory");
}

__device__ __forceinline__ void tma_bulk(uint32_t dst, const float* src,
                                         uint32_t bytes, uint32_t mb)
{
    asm volatile("mbarrier.arrive.expect_tx.shared.b64 _, [%0], %1;"
                 :: "r"(mb), "r"(bytes) : "memory");
    asm volatile("cp.async.bulk.shared::cta.global.mbarrier::complete_tx::bytes "
                 "[%0], [%1], %2, [%3];"
                 :: "r"(dst), "l"(src), "r"(bytes), "r"(mb) : "memory");
}

__device__ __forceinline__ void mbar_wait(uint32_t mb, uint32_t parity)
{
    uint32_t done;
    asm volatile(
        "{\n\t"
        ".reg .pred p;\n\t"
        "mbarrier.try_wait.parity.acquire.cta.shared::cta.b64 p, [%1], %2;\n\t"
        "selp.b32 %0, 1, 0, p;\n\t"
        "}"
        : "=r"(done) : "r"(mb), "r"(parity) : "memory");
    if (!done) {
        asm volatile(
            "{\n\t"
            ".reg .pred P1;\n\t"
            "W%=:\n\t"
            "mbarrier.try_wait.parity.acquire.cta.shared::cta.b64 P1, [%0], %1;\n\t"
            "@P1 bra D%=;\n\t"
            "bra W%=;\n\t"
            "D%=:\n\t"
            "}"
            :: "r"(mb), "r"(parity) : "memory");
    }
}

__global__ __launch_bounds__(TPB)
void cassi_halo2_kernel(const float* __restrict__ x,
                        const float* __restrict__ ca,
                        float* __restrict__ y)
{
    extern __shared__ float smem[];
    float* buf0 = smem;                          // 8192 floats (32KB)
    float* buf1 = buf0 + TN * LL;                // 8192 floats (32KB)
    float* halo = buf1 + TN * LL;                // 4032 floats (16128B)
    float* sca  = halo + HALO_ROWS * LL;         // 512 floats
    float* scah = sca + HALF;                    // 64 floats
    __shared__ __align__(8) uint64_t mbar_store[3];

    const int m   = blockIdx.y;
    const int h   = blockIdx.x;                  // 0 or 1
    const int n0  = h * HALF;
    const int tid = threadIdx.x;

    const float* xbase = x + (size_t)m * (NN * LL);
    const float* xrow  = xbase + (size_t)n0 * LL;
    float*       yrow  = y + (size_t)m * OUTC;

    const uint32_t mb0 = smem_u32(&mbar_store[0]);
    const uint32_t mb1 = smem_u32(&mbar_store[1]);
    const uint32_t mb2 = smem_u32(&mbar_store[2]);
    const uint32_t b0  = smem_u32(buf0);
    const uint32_t b1  = smem_u32(buf1);

    if (tid == 0) {
        mbar_init(mb0, 1);
        mbar_init(mb1, 1);
        mbar_init(mb2, 1);
    }
    __syncthreads();

    if (tid == 0) {
        tma_bulk(b0, xrow,           TILE_BYTES, mb0);
        tma_bulk(b1, xrow + TN * LL, TILE_BYTES, mb1);
        if (h == 1)
            tma_bulk(smem_u32(halo), xbase + (size_t)(n0 - HALO_ROWS) * LL,
                     HALO_BYTES, mb2);
    }

    // Stage ca for this half (+ halo ca for h=1).
    #pragma unroll
    for (int i = tid; i < HALF; i += TPB)
        sca[i] = ca[m * NN + n0 + i];
    if (h == 1 && tid < HALO_ROWS)
        scah[tid] = ca[m * NN + (n0 - HALO_ROWS) + tid];
    __syncthreads();

    // Seed carry for h=1 from the halo tile:
    //   carry[tid] = sum_{k=tid}^{62} halo[k][63+tid-k] * scah[k]
    float carry = 0.0f;
    if (h == 1) {
        mbar_wait(mb2, 0);
        if (tid < HALO_ROWS) {
            #pragma unroll
            for (int k = 0; k < HALO_ROWS; ++k) {
                if (k >= tid)
                    carry = fmaf(halo[k * LL + (HALO_ROWS + tid - k)], scah[k], carry);
            }
        }
    }

    #pragma unroll 1
    for (int t = 0; t < NTIL; ++t) {
        const uint32_t mb     = (t & 1) ? mb1 : mb0;
        const float*   cur    = (t & 1) ? buf1 : buf0;
        const uint32_t parity = (t >> 1) & 1;

        mbar_wait(mb, parity);

        const float* scat = sca + t * TN;
        float accL = carry;                  // carry == 0 for tid >= LL-1
        float accH = 0.0f;
        #pragma unroll
        for (int j = 0; j < LL; ++j) {
            const int  l   = (tid + j) & (LL - 1);
            const bool low = (l <= tid);
            const int  n   = low ? (tid - l) : (tid + TN - l);
            const float v  = cur[n * LL + l];
            if (low) accL = fmaf(v, scat[n], accL);
            else     accH = fmaf(v, scat[n], accH);
        }
        yrow[n0 + t * TN + tid] = accL;
        carry = accH;

        __syncthreads();                     // all threads done reading `cur`

        if (tid == 0 && t + 2 < NTIL) {
            const uint32_t db = (t & 1) ? b1 : b0;
            tma_bulk(db, xrow + (size_t)(t + 2) * TN * LL, TILE_BYTES, mb);
        }
    }

    // Tail: h=1 writes c in [NN, NN+LL-1); h=0's final carry is discarded
    // (those columns are fully computed by h=1 via the halo seed).
    if (h == 1 && tid < LL - 1)
        yrow[NN + tid] = carry;
}

extern "C" void kernel_launch(void* const* d_in, const int* in_sizes, int n_in,
                              void* d_out, int out_size)
{
    const float* x  = (const float*)d_in[0];
    const float* ca = (const float*)d_in[1];
    float* y        = (float*)d_out;

    const int smem_bytes =
        (2 * TN * LL + HALO_ROWS * LL + HALF + 64) * sizeof(float);  // 83968 B

    cudaFuncSetAttribute(cassi_halo2_kernel,
                         cudaFuncAttributeMaxDynamicSharedMemorySize,
                         smem_bytes);

    cassi_halo2_kernel<<<dim3(2, MM), TPB, smem_bytes>>>(x, ca, y);
}